// round 8
// baseline (speedup 1.0000x reference)
#include <cuda_runtime.h>
#include <cstdint>

// x[32,64,112,112] (*) w[128,64,3,3] + b[128] -> out[32,128,112,112], pad=1
// Conv as 9 shifted GEMMs. CTA = (n, oh): D[128 oc][112 px]. 256 thr, 2 CTA/SM.
// All staging via cp.async (zfill padding); A pre-transposed tf32; B truncated fp32.

#define KTOT 576
#define STR  36                          // smem row stride (words): conflict-free ldmatrix
#define RAW_WORDS  (3*114*STR)           // 12312
#define ABUF_WORDS (128*STR)             // 4608
#define SMEM_BYTES ((RAW_WORDS + 2*ABUF_WORDS)*4)   // 86112

__device__ uint32_t Wt[2*9*128*32];      // [half][pass][oc][icl], tf32

__device__ __forceinline__ uint32_t tf32c(float f) {
    uint32_t u; asm("cvt.rna.tf32.f32 %0, %1;" : "=r"(u) : "f"(f)); return u;
}
__device__ __forceinline__ void ldsm4(uint32_t* r, uint32_t addr) {
    asm volatile("ldmatrix.sync.aligned.m8n8.x4.shared.b16 {%0,%1,%2,%3}, [%4];"
                 : "=r"(r[0]), "=r"(r[1]), "=r"(r[2]), "=r"(r[3]) : "r"(addr));
}
__device__ __forceinline__ void ldsm2(uint32_t* r, uint32_t addr) {
    asm volatile("ldmatrix.sync.aligned.m8n8.x2.shared.b16 {%0,%1}, [%2];"
                 : "=r"(r[0]), "=r"(r[1]) : "r"(addr));
}
__device__ __forceinline__ void mma8(float* d, const uint32_t* a, uint32_t b0, uint32_t b1) {
    asm volatile(
        "mma.sync.aligned.m16n8k8.row.col.f32.tf32.tf32.f32 "
        "{%0,%1,%2,%3}, {%4,%5,%6,%7}, {%8,%9}, {%0,%1,%2,%3};"
        : "+f"(d[0]), "+f"(d[1]), "+f"(d[2]), "+f"(d[3])
        : "r"(a[0]), "r"(a[1]), "r"(a[2]), "r"(a[3]), "r"(b0), "r"(b1));
}
__device__ __forceinline__ void cpa16(uint32_t dst, const void* src) {
    asm volatile("cp.async.ca.shared.global [%0], [%1], 16;" :: "r"(dst), "l"(src));
}
__device__ __forceinline__ void cpa4z(uint32_t dst, const void* src, uint32_t sz) {
    asm volatile("cp.async.ca.shared.global [%0], [%1], 4, %2;"
                 :: "r"(dst), "l"(src), "r"(sz));
}
__device__ __forceinline__ void cpa_commit() { asm volatile("cp.async.commit_group;"); }
__device__ __forceinline__ void cpa_wait0()  { asm volatile("cp.async.wait_group 0;" ::: "memory"); }

__global__ void prep_weights(const float* __restrict__ w) {
    const int i = blockIdx.x * 256 + threadIdx.x;     // 73728 total
    const int icl = i & 31;
    const int t   = i >> 5;
    const int oc  = t & 127;
    const int hr  = t >> 7;             // h*9 + r
    const int r   = hr % 9;
    const int h   = hr / 9;
    Wt[i] = tf32c(w[oc * KTOT + (h * 32 + icl) * 9 + r]);
}

__global__ __launch_bounds__(256, 2)
void conv3x3_cpasync(const float* __restrict__ x,
                     const float* __restrict__ bias,
                     float* __restrict__ out)
{
    extern __shared__ uint32_t sm[];

    const int tid = threadIdx.x;
    const int lid = tid & 31;
    const int wid = tid >> 5;
    const int wm  = wid & 3;                     // 32 oc per warp
    const int wn  = wid >> 2;                    // 56 px per warp

    const int bz = blockIdx.x;
    const int n  = bz / 112;
    const int oh = bz - n * 112;

    const uint32_t smem_b = (uint32_t)__cvta_generic_to_shared(sm);
    const uint32_t rawB = smem_b;                          // Raw [342 px][36]
    const uint32_t AsmB = smem_b + RAW_WORDS * 4;          // 2 x [128 oc][36]

    // ldmatrix per-thread offsets (bytes)
    const uint32_t aOff  = AsmB + 4 * ((wm * 32 + (lid & 15)) * STR + ((lid >> 4) << 2));
    const uint32_t bOff4 = 4 * ((lid & 15) * STR + ((lid >> 4) << 2));
    const uint32_t bOff2 = 4 * ((lid & 7) * STR + (((lid >> 3) & 1) << 2));

    float acc[2][7][4];
    #pragma unroll
    for (int mt = 0; mt < 2; ++mt)
        #pragma unroll
        for (int nt = 0; nt < 7; ++nt)
            #pragma unroll
            for (int e = 0; e < 4; ++e) acc[mt][nt][e] = 0.0f;

    // ---- issue A pass tile: 16B cp.async from pre-transposed tf32 weights ----
    auto issue_A = [&](int h, int r, int buf) {
        const uint32_t* src = Wt + (h * 9 + r) * 4096;     // [128][32]
        const int q = tid & 7, ocr = tid >> 3;             // 8 lanes x 16B = 128B runs
        const uint32_t dbase = AsmB + buf * (ABUF_WORDS * 4);
        #pragma unroll
        for (int it = 0; it < 4; ++it) {
            const int oc = it * 32 + ocr;
            cpa16(dbase + 4 * (oc * STR + q * 4), src + oc * 32 + q * 4);
        }
    };

    // ---- issue raw tile for ic-half h: 4B cp.async with zfill padding ----
    // lane map: c8 = tid&7 (col-in-block), icl4 = (tid>>3)&3 -> 4 sectors/instr,
    // conflict-free smem banks (4*c8 + icl4).
    auto issue_raw = [&](int h) {
        const float* xb = x + (size_t)(n * 64 + h * 32) * 12544;
        const int c8 = tid & 7, icl4 = (tid >> 3) & 3, wq = tid >> 5;
        #pragma unroll 1
        for (int combo = wq; combo < 360; combo += 8) {    // row(3) x iclq(8) x cblk(15)
            const int row  = combo / 120;
            const int r2   = combo - row * 120;
            const int iclq = r2 / 15;
            const int cb   = r2 - iclq * 15;
            const int col  = cb * 8 + c8;
            if (col >= 114) continue;
            const int icl = iclq * 4 + icl4;
            const int ih = oh - 1 + row;
            const int iw = col - 1;
            const bool ok = (ih >= 0) & (ih < 112) & (iw >= 0) & (iw < 112);
            const float* src = ok ? (xb + icl * 12544 + ih * 112 + iw) : xb;
            cpa4z(rawB + 4 * ((row * 114 + col) * STR + icl), src, ok ? 4u : 0u);
        }
    };

    // ---- one (kh,kw) GEMM pass, K=32 (identical math to R6) ----
    auto compute = [&](int r, int buf) {
        const int kh = r / 3, kw = r - 3 * kh;
        const uint32_t b4 = rawB + 4 * ((kh * 114 + kw + wn * 56) * STR) + bOff4;
        const uint32_t b2 = rawB + 4 * ((kh * 114 + kw + wn * 56 + 48) * STR) + bOff2;
        const uint32_t aB = aOff + buf * (ABUF_WORDS * 4);
        #pragma unroll
        for (int s = 0; s < 4; ++s) {
            uint32_t a0[4], a1[4];
            ldsm4(a0, aB + s * 32);
            ldsm4(a1, aB + 16 * STR * 4 + s * 32);
            #pragma unroll
            for (int np = 0; np < 3; ++np) {
                uint32_t bf[4];
                ldsm4(bf, b4 + np * (16 * STR * 4) + s * 32);
                #pragma unroll
                for (int half = 0; half < 2; ++half) {
                    const int nt = np * 2 + half;
                    mma8(acc[0][nt], a0, bf[half], bf[2 + half]);
                    mma8(acc[1][nt], a1, bf[half], bf[2 + half]);
                }
            }
            uint32_t bg[2];
            ldsm2(bg, b2 + s * 32);
            mma8(acc[0][6], a0, bg[0], bg[1]);
            mma8(acc[1][6], a1, bg[0], bg[1]);
        }
    };

    // ---- pipelined main loop ----
    issue_raw(0);
    issue_A(0, 0, 0);
    cpa_commit();
    cpa_wait0();
    __syncthreads();

    #pragma unroll 1
    for (int h = 0; h < 2; ++h) {
        #pragma unroll 1
        for (int r = 0; r < 9; ++r) {
            if (r < 8) { issue_A(h, r + 1, (r + 1) & 1); cpa_commit(); }
            compute(r, r & 1);
            if (r < 8) cpa_wait0();
            __syncthreads();
        }
        if (h == 0) {
            issue_raw(1);
            issue_A(1, 0, 0);
            cpa_commit();
            cpa_wait0();
            __syncthreads();
        }
    }

    // ---- epilogue ----
    const int g = lid >> 2, q = lid & 3;
    #pragma unroll
    for (int mt = 0; mt < 2; ++mt) {
        const int oc0 = wm * 32 + mt * 16 + g;
        const float bv0 = bias[oc0];
        const float bv1 = bias[oc0 + 8];
        #pragma unroll
        for (int nt = 0; nt < 7; ++nt) {
            const int col = wn * 56 + nt * 8 + 2 * q;
            float2 v0, v1;
            v0.x = acc[mt][nt][0] + bv0; v0.y = acc[mt][nt][1] + bv0;
            v1.x = acc[mt][nt][2] + bv1; v1.y = acc[mt][nt][3] + bv1;
            float* base = out + (((size_t)n * 128 + oc0) * 112 + oh) * 112 + col;
            *reinterpret_cast<float2*>(base) = v0;
            *reinterpret_cast<float2*>(base + 8 * 112 * 112) = v1;
        }
    }
}

extern "C" void kernel_launch(void* const* d_in, const int* in_sizes, int n_in,
                              void* d_out, int out_size)
{
    const float* x    = (const float*)d_in[0];
    const float* wgt  = (const float*)d_in[1];
    const float* bias = (const float*)d_in[2];
    float* out        = (float*)d_out;

    prep_weights<<<288, 256>>>(wgt);   // one-time weight re-layout + tf32

    cudaFuncSetAttribute(conv3x3_cpasync,
                         cudaFuncAttributeMaxDynamicSharedMemorySize, SMEM_BYTES);
    conv3x3_cpasync<<<32 * 112, 256, SMEM_BYTES>>>(x, bias, out);
}

// round 9
// speedup vs baseline: 1.2162x; 1.2162x over previous
#include <cuda_runtime.h>
#include <cstdint>

// x[32,64,112,112] (*) w[128,64,3,3] + b[128] -> out[32,128,112,112], pad=1
// Conv as 9 shifted GEMMs, CTA = (n, oh): D[128 oc][112 px], 256 thr, 2 CTA/SM.
// Prepass 1: w -> Wt[half][pass][oc][icl] tf32. Prepass 2: x -> Xt[n][h][w][ic] tf32.
// Main kernel stages everything with 16B cp.async (zfill padding); no cvt, no STS.

#define KTOT 576
#define STR  36                          // smem row stride (words): conflict-free ldmatrix
#define RAW_WORDS  (3*114*STR)           // 12312
#define ABUF_WORDS (128*STR)             // 4608
#define SMEM_BYTES ((RAW_WORDS + 2*ABUF_WORDS)*4)   // 86112

__device__ uint32_t Wt[2*9*128*32];                 // tf32 weights, re-laid out
__device__ uint32_t Xt[(size_t)32*112*112*64];      // tf32 input, channels-last

__device__ __forceinline__ uint32_t tf32c(float f) {
    uint32_t u; asm("cvt.rna.tf32.f32 %0, %1;" : "=r"(u) : "f"(f)); return u;
}
__device__ __forceinline__ void ldsm4(uint32_t* r, uint32_t addr) {
    asm volatile("ldmatrix.sync.aligned.m8n8.x4.shared.b16 {%0,%1,%2,%3}, [%4];"
                 : "=r"(r[0]), "=r"(r[1]), "=r"(r[2]), "=r"(r[3]) : "r"(addr));
}
__device__ __forceinline__ void ldsm2(uint32_t* r, uint32_t addr) {
    asm volatile("ldmatrix.sync.aligned.m8n8.x2.shared.b16 {%0,%1}, [%2];"
                 : "=r"(r[0]), "=r"(r[1]) : "r"(addr));
}
__device__ __forceinline__ void mma8(float* d, const uint32_t* a, uint32_t b0, uint32_t b1) {
    asm volatile(
        "mma.sync.aligned.m16n8k8.row.col.f32.tf32.tf32.f32 "
        "{%0,%1,%2,%3}, {%4,%5,%6,%7}, {%8,%9}, {%0,%1,%2,%3};"
        : "+f"(d[0]), "+f"(d[1]), "+f"(d[2]), "+f"(d[3])
        : "r"(a[0]), "r"(a[1]), "r"(a[2]), "r"(a[3]), "r"(b0), "r"(b1));
}
__device__ __forceinline__ void cpa16(uint32_t dst, const void* src) {
    asm volatile("cp.async.ca.shared.global [%0], [%1], 16;" :: "r"(dst), "l"(src));
}
__device__ __forceinline__ void cpa16z(uint32_t dst, const void* src, uint32_t sz) {
    asm volatile("cp.async.ca.shared.global [%0], [%1], 16, %2;"
                 :: "r"(dst), "l"(src), "r"(sz));
}
__device__ __forceinline__ void cpa_commit() { asm volatile("cp.async.commit_group;"); }
__device__ __forceinline__ void cpa_wait0()  { asm volatile("cp.async.wait_group 0;" ::: "memory"); }

__global__ void prep_weights(const float* __restrict__ w) {
    const int i = blockIdx.x * 256 + threadIdx.x;     // 73728 total
    const int icl = i & 31;
    const int t   = i >> 5;
    const int oc  = t & 127;
    const int hr  = t >> 7;
    const int r   = hr % 9;
    const int h   = hr / 9;
    Wt[i] = tf32c(w[oc * KTOT + (h * 32 + icl) * 9 + r]);
}

// x[n][c][h][w] -> Xt[n][h][w][c] (tf32). One (n,h) slice per block.
__global__ __launch_bounds__(256)
void prep_x(const float* __restrict__ x) {
    __shared__ float tile[64][113];
    const int tid = threadIdx.x;
    const int n = blockIdx.x / 112, h = blockIdx.x - (blockIdx.x / 112) * 112;
    const float* src = x + ((size_t)n * 64 * 112 + h) * 112;
    #pragma unroll
    for (int i = tid; i < 64 * 112; i += 256) {       // coalesced along w
        const int c = i / 112, w = i - c * 112;
        tile[c][w] = src[(size_t)c * 12544 + w];
    }
    __syncthreads();
    uint32_t* dst = Xt + ((size_t)(n * 112 + h) * 112) * 64;
    #pragma unroll
    for (int i = tid; i < 112 * 64; i += 256) {       // coalesced along c
        const int w = i >> 6, c = i & 63;
        dst[i] = tf32c(tile[c][w]);                   // smem stride 113: conflict-free
    }
}

__global__ __launch_bounds__(256, 2)
void conv3x3_cpx(const float* __restrict__ bias,
                 float* __restrict__ out)
{
    extern __shared__ uint32_t sm[];

    const int tid = threadIdx.x;
    const int lid = tid & 31;
    const int wid = tid >> 5;
    const int wm  = wid & 3;                     // 32 oc per warp
    const int wn  = wid >> 2;                    // 56 px per warp

    const int bz = blockIdx.x;
    const int n  = bz / 112;
    const int oh = bz - n * 112;

    const uint32_t smem_b = (uint32_t)__cvta_generic_to_shared(sm);
    const uint32_t rawB = smem_b;                          // Raw [342 px][36]
    const uint32_t AsmB = smem_b + RAW_WORDS * 4;          // 2 x [128 oc][36]

    const uint32_t aOff  = AsmB + 4 * ((wm * 32 + (lid & 15)) * STR + ((lid >> 4) << 2));
    const uint32_t bOff4 = 4 * ((lid & 15) * STR + ((lid >> 4) << 2));
    const uint32_t bOff2 = 4 * ((lid & 7) * STR + (((lid >> 3) & 1) << 2));

    float acc[2][7][4];
    #pragma unroll
    for (int mt = 0; mt < 2; ++mt)
        #pragma unroll
        for (int nt = 0; nt < 7; ++nt)
            #pragma unroll
            for (int e = 0; e < 4; ++e) acc[mt][nt][e] = 0.0f;

    // ---- A pass tile: 4x 16B cp.async from Wt ----
    auto issue_A = [&](int h, int r, int buf) {
        const uint32_t* src = Wt + (h * 9 + r) * 4096;     // [128][32]
        const int q = tid & 7, ocr = tid >> 3;
        const uint32_t dbase = AsmB + buf * (ABUF_WORDS * 4);
        #pragma unroll
        for (int it = 0; it < 4; ++it) {
            const int oc = it * 32 + ocr;
            cpa16(dbase + 4 * (oc * STR + q * 4), src + oc * 32 + q * 4);
        }
    };

    // ---- raw tile for ic-half h: one 16B cp.async per (pixel, chunk) ----
    auto issue_raw = [&](int hlf) {
        const uint32_t* xb = Xt + (size_t)n * 12544 * 64 + hlf * 32;
        const int q = tid & 7;                             // 16B chunk within pixel
        #pragma unroll 1
        for (int p = tid >> 3; p < 342; p += 32) {
            const int row = p / 114, col = p - (p / 114) * 114;
            const int ih = oh - 1 + row;
            const int iw = col - 1;
            const bool ok = (ih >= 0) & (ih < 112) & (iw >= 0) & (iw < 112);
            const uint32_t* src = ok ? xb + ((size_t)ih * 112 + iw) * 64 + q * 4 : Xt;
            cpa16z(rawB + 4 * ((row * 114 + col) * STR + q * 4), src, ok ? 16u : 0u);
        }
    };

    // ---- one (kh,kw) GEMM pass, K=32 (identical math to R6) ----
    auto compute = [&](int r, int buf) {
        const int kh = r / 3, kw = r - 3 * kh;
        const uint32_t b4 = rawB + 4 * ((kh * 114 + kw + wn * 56) * STR) + bOff4;
        const uint32_t b2 = rawB + 4 * ((kh * 114 + kw + wn * 56 + 48) * STR) + bOff2;
        const uint32_t aB = aOff + buf * (ABUF_WORDS * 4);
        #pragma unroll
        for (int s = 0; s < 4; ++s) {
            uint32_t a0[4], a1[4];
            ldsm4(a0, aB + s * 32);
            ldsm4(a1, aB + 16 * STR * 4 + s * 32);
            #pragma unroll
            for (int np = 0; np < 3; ++np) {
                uint32_t bf[4];
                ldsm4(bf, b4 + np * (16 * STR * 4) + s * 32);
                #pragma unroll
                for (int half = 0; half < 2; ++half) {
                    const int nt = np * 2 + half;
                    mma8(acc[0][nt], a0, bf[half], bf[2 + half]);
                    mma8(acc[1][nt], a1, bf[half], bf[2 + half]);
                }
            }
            uint32_t bg[2];
            ldsm2(bg, b2 + s * 32);
            mma8(acc[0][6], a0, bg[0], bg[1]);
            mma8(acc[1][6], a1, bg[0], bg[1]);
        }
    };

    // ---- pipelined main loop ----
    issue_raw(0);
    issue_A(0, 0, 0);
    cpa_commit();
    cpa_wait0();
    __syncthreads();

    #pragma unroll 1
    for (int h = 0; h < 2; ++h) {
        #pragma unroll 1
        for (int r = 0; r < 9; ++r) {
            if (r < 8) { issue_A(h, r + 1, (r + 1) & 1); cpa_commit(); }
            compute(r, r & 1);
            if (r < 8) cpa_wait0();
            __syncthreads();
        }
        if (h == 0) {
            issue_raw(1);
            issue_A(1, 0, 0);
            cpa_commit();
            cpa_wait0();
            __syncthreads();
        }
    }

    // ---- epilogue ----
    const int g = lid >> 2, q = lid & 3;
    #pragma unroll
    for (int mt = 0; mt < 2; ++mt) {
        const int oc0 = wm * 32 + mt * 16 + g;
        const float bv0 = bias[oc0];
        const float bv1 = bias[oc0 + 8];
        #pragma unroll
        for (int nt = 0; nt < 7; ++nt) {
            const int col = wn * 56 + nt * 8 + 2 * q;
            float2 v0, v1;
            v0.x = acc[mt][nt][0] + bv0; v0.y = acc[mt][nt][1] + bv0;
            v1.x = acc[mt][nt][2] + bv1; v1.y = acc[mt][nt][3] + bv1;
            float* base = out + (((size_t)n * 128 + oc0) * 112 + oh) * 112 + col;
            *reinterpret_cast<float2*>(base) = v0;
            *reinterpret_cast<float2*>(base + 8 * 112 * 112) = v1;
        }
    }
}

extern "C" void kernel_launch(void* const* d_in, const int* in_sizes, int n_in,
                              void* d_out, int out_size)
{
    const float* x    = (const float*)d_in[0];
    const float* wgt  = (const float*)d_in[1];
    const float* bias = (const float*)d_in[2];
    float* out        = (float*)d_out;

    prep_weights<<<288, 256>>>(wgt);
    prep_x<<<32 * 112, 256>>>(x);

    cudaFuncSetAttribute(conv3x3_cpx,
                         cudaFuncAttributeMaxDynamicSharedMemorySize, SMEM_BYTES);
    conv3x3_cpx<<<32 * 112, 256, SMEM_BYTES>>>(bias, out);
}

// round 10
// speedup vs baseline: 1.9348x; 1.5909x over previous
#include <cuda_runtime.h>
#include <cuda_fp16.h>
#include <cstdint>

// x[32,64,112,112] (*) w[128,64,3,3] + b[128] -> out[32,128,112,112], pad=1
// Conv as 9 shifted GEMMs, CTA = (n, oh): D[128 oc][112 px], 256 thr, 2 CTA/SM.
// fp16 mma m16n8k16 (f32 accum). Prepass: w -> Wt fp16 re-laid; x -> Xt fp16 NHWC.
// All smem staging via 16B cp.async (zfill for padding); no cvt/STS in main kernel.

#define KTOT 576
#define STRB 80                           // smem row stride (bytes): conflict-free ldsm
#define RAW_BYTES  (342*STRB)             // 27360
#define ABUF_BYTES (128*STRB)             // 10240
#define SMEM_BYTES (RAW_BYTES + 2*ABUF_BYTES)   // 47840

__device__ __align__(16) __half Wt[2*9*128*32];              // re-laid weights
__device__ __align__(16) __half Xt[(size_t)32*112*112*64];   // NHWC input

__device__ __forceinline__ void ldsm4(uint32_t* r, uint32_t addr) {
    asm volatile("ldmatrix.sync.aligned.m8n8.x4.shared.b16 {%0,%1,%2,%3}, [%4];"
                 : "=r"(r[0]), "=r"(r[1]), "=r"(r[2]), "=r"(r[3]) : "r"(addr));
}
__device__ __forceinline__ void ldsm2(uint32_t* r, uint32_t addr) {
    asm volatile("ldmatrix.sync.aligned.m8n8.x2.shared.b16 {%0,%1}, [%2];"
                 : "=r"(r[0]), "=r"(r[1]) : "r"(addr));
}
__device__ __forceinline__ void mma16(float* d, const uint32_t* a, uint32_t b0, uint32_t b1) {
    asm volatile(
        "mma.sync.aligned.m16n8k16.row.col.f32.f16.f16.f32 "
        "{%0,%1,%2,%3}, {%4,%5,%6,%7}, {%8,%9}, {%0,%1,%2,%3};"
        : "+f"(d[0]), "+f"(d[1]), "+f"(d[2]), "+f"(d[3])
        : "r"(a[0]), "r"(a[1]), "r"(a[2]), "r"(a[3]), "r"(b0), "r"(b1));
}
__device__ __forceinline__ void cpa16(uint32_t dst, const void* src) {
    asm volatile("cp.async.ca.shared.global [%0], [%1], 16;" :: "r"(dst), "l"(src));
}
__device__ __forceinline__ void cpa16z(uint32_t dst, const void* src, uint32_t sz) {
    asm volatile("cp.async.ca.shared.global [%0], [%1], 16, %2;"
                 :: "r"(dst), "l"(src), "r"(sz));
}
__device__ __forceinline__ void cpa_commit() { asm volatile("cp.async.commit_group;"); }
__device__ __forceinline__ void cpa_wait0()  { asm volatile("cp.async.wait_group 0;" ::: "memory"); }

__global__ void prep_weights(const float* __restrict__ w) {
    const int i = blockIdx.x * 256 + threadIdx.x;     // 73728 total
    const int icl = i & 31;
    const int t   = i >> 5;
    const int oc  = t & 127;
    const int hr  = t >> 7;
    const int r   = hr % 9;
    const int h   = hr / 9;
    Wt[i] = __float2half_rn(w[oc * KTOT + (h * 32 + icl) * 9 + r]);
}

// x[n][c][h][w] -> Xt[n][h][w][c] fp16. One (n,h) slice per block.
__global__ __launch_bounds__(256)
void prep_x(const float* __restrict__ x) {
    __shared__ float tile[64][113];
    const int tid = threadIdx.x;
    const int n = blockIdx.x / 112, h = blockIdx.x - n * 112;
    const float* src = x + ((size_t)n * 64 * 112 + h) * 112;
    #pragma unroll
    for (int i = tid; i < 64 * 112; i += 256) {        // coalesced along w
        const int c = i / 112, w = i - c * 112;
        tile[c][w] = src[(size_t)c * 12544 + w];
    }
    __syncthreads();
    __half2* dst = reinterpret_cast<__half2*>(Xt + ((size_t)(n * 112 + h) * 112) * 64);
    #pragma unroll
    for (int i = tid; i < 112 * 32; i += 256) {        // coalesced along c
        const int w = i >> 5, c2 = i & 31;
        dst[i] = __floats2half2_rn(tile[2 * c2][w], tile[2 * c2 + 1][w]);
    }
}

__global__ __launch_bounds__(256, 2)
void conv3x3_fp16(const float* __restrict__ bias,
                  float* __restrict__ out)
{
    extern __shared__ uint32_t sm[];

    const int tid = threadIdx.x;
    const int lid = tid & 31;
    const int wid = tid >> 5;
    const int wm  = wid & 3;                     // 32 oc per warp
    const int wn  = wid >> 2;                    // 56 px per warp

    const int bz = blockIdx.x;
    const int n  = bz / 112;
    const int oh = bz - n * 112;

    const uint32_t smem_b = (uint32_t)__cvta_generic_to_shared(sm);
    const uint32_t rawB = smem_b;                          // Raw [342 px][80B]
    const uint32_t AsmB = smem_b + RAW_BYTES;              // 2 x [128 oc][80B]

    // ldmatrix per-thread offsets (bytes); k-split at +16B
    const uint32_t aOff  = AsmB + (wm * 32 + (lid & 15)) * STRB + ((lid >> 4) << 4);
    const uint32_t bOff4 = (lid & 15) * STRB + ((lid >> 4) << 4);
    const uint32_t bOff2 = (lid & 7) * STRB + (((lid >> 3) & 1) << 4);

    float acc[2][7][4];
    #pragma unroll
    for (int mt = 0; mt < 2; ++mt)
        #pragma unroll
        for (int nt = 0; nt < 7; ++nt)
            #pragma unroll
            for (int e = 0; e < 4; ++e) acc[mt][nt][e] = 0.0f;

    // ---- A pass tile: 2x 16B cp.async from Wt (128 rows x 64B) ----
    auto issue_A = [&](int h, int r, int buf) {
        const __half* src = Wt + (h * 9 + r) * 4096;       // [128][32] halves
        const int q = tid & 3, ocr = tid >> 2;             // 4 chunks x 64 rows
        const uint32_t dbase = AsmB + buf * ABUF_BYTES;
        #pragma unroll
        for (int it = 0; it < 2; ++it) {
            const int oc = it * 64 + ocr;
            cpa16(dbase + oc * STRB + q * 16, src + oc * 32 + q * 8);
        }
    };

    // ---- raw tile for ic-half h: one 16B cp.async per (pixel, 8-ic chunk) ----
    auto issue_raw = [&](int hlf) {
        const __half* xb = Xt + (size_t)n * 12544 * 64 + hlf * 32;
        const int q = tid & 3;
        #pragma unroll 1
        for (int p = tid >> 2; p < 342; p += 64) {
            const int row = p / 114, col = p - row * 114;
            const int ih = oh - 1 + row;
            const int iw = col - 1;
            const bool ok = (ih >= 0) & (ih < 112) & (iw >= 0) & (iw < 112);
            const __half* src = ok ? xb + ((size_t)ih * 112 + iw) * 64 + q * 8 : Xt;
            cpa16z(rawB + p * STRB + q * 16, src, ok ? 16u : 0u);
        }
    };

    // ---- one (kh,kw) GEMM pass, K=32 (2 k16 mma steps) ----
    auto compute = [&](int r, int buf) {
        const int kh = r / 3, kw = r - 3 * kh;
        const uint32_t b4 = rawB + (kh * 114 + kw + wn * 56) * STRB + bOff4;
        const uint32_t b2 = rawB + (kh * 114 + kw + wn * 56 + 48) * STRB + bOff2;
        const uint32_t aB = aOff + buf * ABUF_BYTES;
        #pragma unroll
        for (int s = 0; s < 2; ++s) {
            uint32_t a0[4], a1[4];
            ldsm4(a0, aB + s * 32);
            ldsm4(a1, aB + 16 * STRB + s * 32);
            #pragma unroll
            for (int np = 0; np < 3; ++np) {
                uint32_t bf[4];
                ldsm4(bf, b4 + np * (16 * STRB) + s * 32);
                #pragma unroll
                for (int half = 0; half < 2; ++half) {
                    const int nt = np * 2 + half;
                    mma16(acc[0][nt], a0, bf[half], bf[2 + half]);
                    mma16(acc[1][nt], a1, bf[half], bf[2 + half]);
                }
            }
            uint32_t bg[2];
            ldsm2(bg, b2 + s * 32);
            mma16(acc[0][6], a0, bg[0], bg[1]);
            mma16(acc[1][6], a1, bg[0], bg[1]);
        }
    };

    // ---- pipelined main loop ----
    issue_raw(0);
    issue_A(0, 0, 0);
    cpa_commit();
    cpa_wait0();
    __syncthreads();

    #pragma unroll 1
    for (int h = 0; h < 2; ++h) {
        #pragma unroll 1
        for (int r = 0; r < 9; ++r) {
            if (r < 8) { issue_A(h, r + 1, (r + 1) & 1); cpa_commit(); }
            compute(r, r & 1);
            if (r < 8) cpa_wait0();
            __syncthreads();
        }
        if (h == 0) {
            issue_raw(1);
            issue_A(1, 0, 0);
            cpa_commit();
            cpa_wait0();
            __syncthreads();
        }
    }

    // ---- epilogue ----
    const int g = lid >> 2, q = lid & 3;
    #pragma unroll
    for (int mt = 0; mt < 2; ++mt) {
        const int oc0 = wm * 32 + mt * 16 + g;
        const float bv0 = bias[oc0];
        const float bv1 = bias[oc0 + 8];
        #pragma unroll
        for (int nt = 0; nt < 7; ++nt) {
            const int col = wn * 56 + nt * 8 + 2 * q;
            float2 v0, v1;
            v0.x = acc[mt][nt][0] + bv0; v0.y = acc[mt][nt][1] + bv0;
            v1.x = acc[mt][nt][2] + bv1; v1.y = acc[mt][nt][3] + bv1;
            float* base = out + (((size_t)n * 128 + oc0) * 112 + oh) * 112 + col;
            *reinterpret_cast<float2*>(base) = v0;
            *reinterpret_cast<float2*>(base + 8 * 112 * 112) = v1;
        }
    }
}

extern "C" void kernel_launch(void* const* d_in, const int* in_sizes, int n_in,
                              void* d_out, int out_size)
{
    const float* x    = (const float*)d_in[0];
    const float* wgt  = (const float*)d_in[1];
    const float* bias = (const float*)d_in[2];
    float* out        = (float*)d_out;

    prep_weights<<<288, 256>>>(wgt);
    prep_x<<<32 * 112, 256>>>(x);

    cudaFuncSetAttribute(conv3x3_fp16,
                         cudaFuncAttributeMaxDynamicSharedMemorySize, SMEM_BYTES);
    conv3x3_fp16<<<32 * 112, 256, SMEM_BYTES>>>(bias, out);
}